// round 3
// baseline (speedup 1.0000x reference)
#include <cuda_runtime.h>

#define NBT 16320  // 64 * 255

// compact exp blocks: g_expT[bt*512 + k*64 + c*8 + r] = E_k[r][c], bt = b*255+t
__device__ float g_expT[NBT * 512];

static __device__ __forceinline__ unsigned long long pk2(float lo, float hi) {
    unsigned long long r;
    asm("mov.b64 %0, {%1,%2};" : "=l"(r) : "f"(lo), "f"(hi));
    return r;
}
static __device__ __forceinline__ void upk2(unsigned long long v, float& lo, float& hi) {
    asm("mov.b64 {%0,%1}, %2;" : "=f"(lo), "=f"(hi) : "l"(v));
}
static __device__ __forceinline__ unsigned long long fma2_(unsigned long long a,
                                                           unsigned long long b,
                                                           unsigned long long c) {
    unsigned long long d;
    asm("fma.rn.f32x2 %0, %1, %2, %3;" : "=l"(d) : "l"(a), "l"(b), "l"(c));
    return d;
}

// ---------------- encoder: latent = obs(16384x512) @ We(512x64) + be -------
__global__ void __launch_bounds__(128) k_enc(const float* __restrict__ obs,
                                             const float* __restrict__ We,
                                             const float* __restrict__ be,
                                             float* __restrict__ latent) {
    __shared__ __align__(16) float obsS[64 * 68];
    __shared__ __align__(16) float Wsm[64 * 64];
    const int tid = threadIdx.x;
    const int tx = tid & 7, ty = tid >> 3;
    const int row0 = blockIdx.x * 64;

    unsigned long long acc[4][4];
    {
        const int cb = tx * 8;
        unsigned long long b0 = pk2(be[cb + 0], be[cb + 1]);
        unsigned long long b1 = pk2(be[cb + 2], be[cb + 3]);
        unsigned long long b2 = pk2(be[cb + 4], be[cb + 5]);
        unsigned long long b3 = pk2(be[cb + 6], be[cb + 7]);
#pragma unroll
        for (int r = 0; r < 4; r++) {
            acc[r][0] = b0; acc[r][1] = b1; acc[r][2] = b2; acc[r][3] = b3;
        }
    }
    for (int kc = 0; kc < 8; kc++) {
#pragma unroll
        for (int i = tid; i < 1024; i += 128) {
            int rr = i >> 4, c4 = (i & 15) * 4;
            *(float4*)&obsS[rr * 68 + c4] =
                *(const float4*)&obs[(size_t)(row0 + rr) * 512 + kc * 64 + c4];
        }
#pragma unroll
        for (int i = tid; i < 1024; i += 128) {
            int rk = i >> 4, c4 = (i & 15) * 4;
            *(float4*)&Wsm[rk * 64 + c4] =
                *(const float4*)&We[(size_t)(kc * 64 + rk) * 64 + c4];
        }
        __syncthreads();
#pragma unroll 8
        for (int k = 0; k < 64; k++) {
            ulonglong2 wA = *(const ulonglong2*)&Wsm[k * 64 + tx * 8];
            ulonglong2 wB = *(const ulonglong2*)&Wsm[k * 64 + tx * 8 + 4];
#pragma unroll
            for (int r = 0; r < 4; r++) {
                float o = obsS[(ty + r * 16) * 68 + k];
                unsigned long long o2 = pk2(o, o);
                acc[r][0] = fma2_(o2, wA.x, acc[r][0]);
                acc[r][1] = fma2_(o2, wA.y, acc[r][1]);
                acc[r][2] = fma2_(o2, wB.x, acc[r][2]);
                acc[r][3] = fma2_(o2, wB.y, acc[r][3]);
            }
        }
        __syncthreads();
    }
#pragma unroll
    for (int r = 0; r < 4; r++) {
        float v0, v1, v2, v3, v4, v5, v6, v7;
        upk2(acc[r][0], v0, v1); upk2(acc[r][1], v2, v3);
        upk2(acc[r][2], v4, v5); upk2(acc[r][3], v6, v7);
        float* dst = &latent[(size_t)(row0 + ty + r * 16) * 64 + tx * 8];
        *(float4*)dst = make_float4(v0, v1, v2, v3);
        *(float4*)(dst + 4) = make_float4(v4, v5, v6, v7);
    }
}

// ---------------- phi GEMM + expm + rho ------------------------------------
__global__ void __launch_bounds__(256) k_phi(const float* __restrict__ act,
                                             const float* __restrict__ Wp,
                                             const float* __restrict__ bp,
                                             float* __restrict__ rho) {
    __shared__ __align__(16) float actS[4][32];
    __shared__ __align__(16) float Ablk[32 * 68];  // A blocks, [g][r*8+c], padded
    __shared__ __align__(16) float Esm[32 * 72];   // exp blocks, [g][r*8+c], padded
    const int tid = threadIdx.x;
    const int bt0 = blockIdx.x * 4;

    for (int i = tid; i < 128; i += 256)
        actS[i >> 5][i & 31] = act[(size_t)bt0 * 32 + i];
    __syncthreads();

    // after_phi = act @ Wp + bp, stored transposed-per-block into Ablk
#pragma unroll
    for (int jj = 0; jj < 2; jj++) {
        const int j = tid + jj * 256;
        float wc[32];
#pragma unroll
        for (int a = 0; a < 32; a++) wc[a] = Wp[a * 512 + j];
        const float bb = bp[j];
        const int k = j >> 6, rowj = (j >> 3) & 7, colj = j & 7;
#pragma unroll
        for (int lbt = 0; lbt < 4; lbt++) {
            float s = bb;
#pragma unroll
            for (int a = 0; a < 32; a++) s = fmaf(actS[lbt][a], wc[a], s);
            // blocks.transpose(0,2,1): A[colj][rowj] = after_phi[j]
            Ablk[(lbt * 8 + k) * 68 + colj * 8 + rowj] = s;
        }
    }
    __syncthreads();

    // expm: group g (8 lanes), lane lc owns column lc. A scaled by 1/8.
    const int g = tid >> 3, lc = tid & 7;
    float A[64];
#pragma unroll
    for (int i = 0; i < 16; i++) {
        float4 v = *(const float4*)&Ablk[g * 68 + i * 4];
        A[i * 4 + 0] = v.x * 0.125f; A[i * 4 + 1] = v.y * 0.125f;
        A[i * 4 + 2] = v.z * 0.125f; A[i * 4 + 3] = v.w * 0.125f;
    }
    float Rc[8];
#pragma unroll
    for (int rr = 0; rr < 8; rr++) Rc[rr] = A[rr * 8 + lc] * 0.125f;
    Rc[lc] += 1.0f;
#pragma unroll
    for (int m = 7; m >= 1; m--) {   // R <- I + (A*R)/m   (Taylor-8 Horner)
        float t[8];
#pragma unroll
        for (int rr = 0; rr < 8; rr++) {
            float s = 0.0f;
#pragma unroll
            for (int kk = 0; kk < 8; kk++) s = fmaf(A[rr * 8 + kk], Rc[kk], s);
            t[rr] = s;
        }
        const float inv = 1.0f / (float)m;
#pragma unroll
        for (int rr = 0; rr < 8; rr++) Rc[rr] = t[rr] * inv;
        Rc[lc] += 1.0f;
    }
#pragma unroll
    for (int sq = 0; sq < 3; sq++) {   // R <- R*R (undo 1/8 scaling)
        float t[8] = {0, 0, 0, 0, 0, 0, 0, 0};
#pragma unroll
        for (int j = 0; j < 8; j++) {
            float colj[8];
#pragma unroll
            for (int rr = 0; rr < 8; rr++)
                colj[rr] = __shfl_sync(0xffffffffu, Rc[rr], j, 8);
            const float s = Rc[j];
#pragma unroll
            for (int rr = 0; rr < 8; rr++) t[rr] = fmaf(colj[rr], s, t[rr]);
        }
#pragma unroll
        for (int rr = 0; rr < 8; rr++) Rc[rr] = t[rr];
    }
#pragma unroll
    for (int rr = 0; rr < 8; rr++) Esm[g * 72 + rr * 8 + lc] = Rc[rr];
    __syncthreads();

    // compact column-major copy for recurrence
#pragma unroll
    for (int i = tid; i < 2048; i += 256) {
        int lbt = i >> 9, q = i & 511;
        int k = q >> 6, cq = (q >> 3) & 7, rq = q & 7;
        g_expT[(size_t)(bt0 + lbt) * 512 + q] = Esm[(lbt * 8 + k) * 72 + rq * 8 + cq];
    }
    // rho: fully coalesced float4 stream (zeros + diagonal blocks)
#pragma unroll
    for (int i = tid; i < 4096; i += 256) {
        int lbt = i >> 10, rem = i & 1023, row = rem >> 4, q = rem & 15;
        int k = row >> 3;
        float4 v = make_float4(0.f, 0.f, 0.f, 0.f);
        if ((q >> 1) == k)
            v = *(const float4*)&Esm[(lbt * 8 + k) * 72 + (row & 7) * 8 + (q & 1) * 4];
        ((float4*)rho)[((size_t)(bt0 + lbt) * 64 + row) * 16 + q] = v;
    }
}

// ---------------- recurrence -----------------------------------------------
__global__ void __launch_bounds__(64) k_rec(const float* __restrict__ latent,
                                            float* __restrict__ pred) {
    const int b = blockIdx.x, c = threadIdx.x;
    const int k = c >> 3, cc = c & 7;
    float h = latent[(size_t)b * 256 * 64 + c];
    pred[(size_t)b * 256 * 64 + c] = h;
    const float4* base = (const float4*)&g_expT[(size_t)b * 255 * 512];
    const int off = k * 16 + cc * 2;
    float4 e0 = base[off], e1 = base[off + 1];
    for (int t = 0; t < 255; t++) {
        const int tn = (t + 1 < 255) ? (t + 1) : 254;
        float4 n0 = base[tn * 128 + off];
        float4 n1 = base[tn * 128 + off + 1];
        float s0 = __shfl_sync(0xffffffffu, h, 0, 8) * e0.x;
        float s1 = __shfl_sync(0xffffffffu, h, 1, 8) * e0.y;
        s0 = fmaf(__shfl_sync(0xffffffffu, h, 2, 8), e0.z, s0);
        s1 = fmaf(__shfl_sync(0xffffffffu, h, 3, 8), e0.w, s1);
        s0 = fmaf(__shfl_sync(0xffffffffu, h, 4, 8), e1.x, s0);
        s1 = fmaf(__shfl_sync(0xffffffffu, h, 5, 8), e1.y, s1);
        s0 = fmaf(__shfl_sync(0xffffffffu, h, 6, 8), e1.z, s0);
        s1 = fmaf(__shfl_sync(0xffffffffu, h, 7, 8), e1.w, s1);
        h = s0 + s1;
        pred[((size_t)b * 256 + t + 1) * 64 + c] = h;
        e0 = n0; e1 = n1;
    }
}

// ---------------- decoder: pred_obs = pred_lat(16384x64) @ Wd(64x512) + bd --
__global__ void __launch_bounds__(128) k_dec(const float* __restrict__ lat,
                                             const float* __restrict__ Wd,
                                             const float* __restrict__ bd,
                                             float* __restrict__ out) {
    __shared__ __align__(16) float latS[64 * 68];
    __shared__ __align__(16) float Wsm[64 * 64];
    const int tid = threadIdx.x;
    const int tx = tid & 7, ty = tid >> 3;
    const int row0 = blockIdx.x * 64;
    const int col0 = blockIdx.y * 64;

    for (int i = tid; i < 1024; i += 128) {
        int rr = i >> 4, c4 = (i & 15) * 4;
        *(float4*)&latS[rr * 68 + c4] =
            *(const float4*)&lat[(size_t)(row0 + rr) * 64 + c4];
    }
    for (int i = tid; i < 1024; i += 128) {
        int rk = i >> 4, c4 = (i & 15) * 4;
        *(float4*)&Wsm[rk * 64 + c4] =
            *(const float4*)&Wd[(size_t)rk * 512 + col0 + c4];
    }
    unsigned long long acc[4][4];
    {
        const int cb = col0 + tx * 8;
        unsigned long long b0 = pk2(bd[cb + 0], bd[cb + 1]);
        unsigned long long b1 = pk2(bd[cb + 2], bd[cb + 3]);
        unsigned long long b2 = pk2(bd[cb + 4], bd[cb + 5]);
        unsigned long long b3 = pk2(bd[cb + 6], bd[cb + 7]);
#pragma unroll
        for (int r = 0; r < 4; r++) {
            acc[r][0] = b0; acc[r][1] = b1; acc[r][2] = b2; acc[r][3] = b3;
        }
    }
    __syncthreads();
#pragma unroll 8
    for (int k = 0; k < 64; k++) {
        ulonglong2 wA = *(const ulonglong2*)&Wsm[k * 64 + tx * 8];
        ulonglong2 wB = *(const ulonglong2*)&Wsm[k * 64 + tx * 8 + 4];
#pragma unroll
        for (int r = 0; r < 4; r++) {
            float o = latS[(ty + r * 16) * 68 + k];
            unsigned long long o2 = pk2(o, o);
            acc[r][0] = fma2_(o2, wA.x, acc[r][0]);
            acc[r][1] = fma2_(o2, wA.y, acc[r][1]);
            acc[r][2] = fma2_(o2, wB.x, acc[r][2]);
            acc[r][3] = fma2_(o2, wB.y, acc[r][3]);
        }
    }
#pragma unroll
    for (int r = 0; r < 4; r++) {
        float v0, v1, v2, v3, v4, v5, v6, v7;
        upk2(acc[r][0], v0, v1); upk2(acc[r][1], v2, v3);
        upk2(acc[r][2], v4, v5); upk2(acc[r][3], v6, v7);
        float* dst = &out[(size_t)(row0 + ty + r * 16) * 512 + col0 + tx * 8];
        *(float4*)dst = make_float4(v0, v1, v2, v3);
        *(float4*)(dst + 4) = make_float4(v4, v5, v6, v7);
    }
}

extern "C" void kernel_launch(void* const* d_in, const int* in_sizes, int n_in,
                              void* d_out, int out_size) {
    const float* obs = (const float*)d_in[0];
    const float* act = (const float*)d_in[1];
    const float* We  = (const float*)d_in[2];
    const float* be  = (const float*)d_in[3];
    const float* Wd  = (const float*)d_in[4];
    const float* bd  = (const float*)d_in[5];
    const float* Wp  = (const float*)d_in[6];
    const float* bp  = (const float*)d_in[7];
    float* out = (float*)d_out;

    float* latent   = out;                 // [64,256,64]
    float* rho      = out + 1048576;       // [64,255,64,64]
    float* pred_lat = out + 67895296;      // [64,256,64]
    float* pred_obs = out + 68943872;      // [64,256,512]

    k_enc<<<256, 128>>>(obs, We, be, latent);
    k_phi<<<4080, 256>>>(act, Wp, bp, rho);
    k_rec<<<64, 64>>>(latent, pred_lat);
    k_dec<<<dim3(256, 8), 128>>>(pred_lat, Wd, bd, pred_obs);
}

// round 6
// speedup vs baseline: 1.9368x; 1.9368x over previous
#include <cuda_runtime.h>

#define NBT 16320  // 64 * 255

// compact exp blocks: g_expT[bt*512 + k*64 + c*8 + r] = E_k[r][c], bt = b*255+t
__device__ float g_expT[NBT * 512];

static __device__ __forceinline__ unsigned long long pk2(float lo, float hi) {
    unsigned long long r;
    asm("mov.b64 %0, {%1,%2};" : "=l"(r) : "f"(lo), "f"(hi));
    return r;
}
static __device__ __forceinline__ void upk2(unsigned long long v, float& lo, float& hi) {
    asm("mov.b64 {%0,%1}, %2;" : "=f"(lo), "=f"(hi) : "l"(v));
}
static __device__ __forceinline__ unsigned long long fma2_(unsigned long long a,
                                                           unsigned long long b,
                                                           unsigned long long c) {
    unsigned long long d;
    asm("fma.rn.f32x2 %0, %1, %2, %3;" : "=l"(d) : "l"(a), "l"(b), "l"(c));
    return d;
}

// ---------------- encoder: latent = obs(16384x512) @ We(512x64) + be -------
// 64x64 tile, 128 thr, thread = 4 rows x 8 cols. Register double-buffered K
// chunks; W stored bank-swizzled: chunk (q,tx) (q=0,1) at (q*8+tx)*4 floats.
__global__ void __launch_bounds__(128) k_enc(const float* __restrict__ obs,
                                             const float* __restrict__ We,
                                             const float* __restrict__ be,
                                             float* __restrict__ latent) {
    __shared__ __align__(16) float obsS[64 * 68];
    __shared__ __align__(16) float Wsm[64 * 64];
    const int tid = threadIdx.x;
    const int tx = tid & 7, ty = tid >> 3;
    const int row0 = blockIdx.x * 64;

    unsigned long long acc[4][4];
    {
        const int cb = tx * 8;
        unsigned long long b0 = pk2(be[cb + 0], be[cb + 1]);
        unsigned long long b1 = pk2(be[cb + 2], be[cb + 3]);
        unsigned long long b2 = pk2(be[cb + 4], be[cb + 5]);
        unsigned long long b3 = pk2(be[cb + 6], be[cb + 7]);
#pragma unroll
        for (int r = 0; r < 4; r++) {
            acc[r][0] = b0; acc[r][1] = b1; acc[r][2] = b2; acc[r][3] = b3;
        }
    }

    float4 rA[8], rW[8];
#pragma unroll
    for (int n = 0; n < 8; n++) {
        int i = tid + n * 128;
        int rr = i >> 4, c4 = (i & 15) * 4;
        rA[n] = *(const float4*)&obs[(size_t)(row0 + rr) * 512 + c4];
        rW[n] = *(const float4*)&We[(size_t)rr * 64 + c4];
    }
    for (int kc = 0; kc < 8; kc++) {
#pragma unroll
        for (int n = 0; n < 8; n++) {
            int i = tid + n * 128;
            int rr = i >> 4, c4 = (i & 15) * 4;
            *(float4*)&obsS[rr * 68 + c4] = rA[n];
            int q = (c4 >> 2) & 1, txc = c4 >> 3;
            *(float4*)&Wsm[rr * 64 + (q * 8 + txc) * 4] = rW[n];
        }
        __syncthreads();
        if (kc < 7) {
#pragma unroll
            for (int n = 0; n < 8; n++) {
                int i = tid + n * 128;
                int rr = i >> 4, c4 = (i & 15) * 4;
                rA[n] = *(const float4*)&obs[(size_t)(row0 + rr) * 512 + (kc + 1) * 64 + c4];
                rW[n] = *(const float4*)&We[(size_t)((kc + 1) * 64 + rr) * 64 + c4];
            }
        }
#pragma unroll
        for (int k4 = 0; k4 < 16; k4++) {
            float4 o4[4];
#pragma unroll
            for (int r = 0; r < 4; r++)
                o4[r] = *(const float4*)&obsS[(ty + r * 16) * 68 + k4 * 4];
#pragma unroll
            for (int kk = 0; kk < 4; kk++) {
                int k = k4 * 4 + kk;
                ulonglong2 w0 = *(const ulonglong2*)&Wsm[k * 64 + tx * 4];
                ulonglong2 w1 = *(const ulonglong2*)&Wsm[k * 64 + (8 + tx) * 4];
#pragma unroll
                for (int r = 0; r < 4; r++) {
                    float o = (kk == 0) ? o4[r].x : (kk == 1) ? o4[r].y
                              : (kk == 2) ? o4[r].z : o4[r].w;
                    unsigned long long o2 = pk2(o, o);
                    acc[r][0] = fma2_(o2, w0.x, acc[r][0]);
                    acc[r][1] = fma2_(o2, w0.y, acc[r][1]);
                    acc[r][2] = fma2_(o2, w1.x, acc[r][2]);
                    acc[r][3] = fma2_(o2, w1.y, acc[r][3]);
                }
            }
        }
        __syncthreads();
    }
#pragma unroll
    for (int r = 0; r < 4; r++) {
        float v0, v1, v2, v3, v4, v5, v6, v7;
        upk2(acc[r][0], v0, v1); upk2(acc[r][1], v2, v3);
        upk2(acc[r][2], v4, v5); upk2(acc[r][3], v6, v7);
        float* dst = &latent[(size_t)(row0 + ty + r * 16) * 64 + tx * 8];
        *(float4*)dst = make_float4(v0, v1, v2, v3);
        *(float4*)(dst + 4) = make_float4(v4, v5, v6, v7);
    }
}

// ---------------- phi GEMM + expm + rho ------------------------------------
__global__ void __launch_bounds__(256) k_phi(const float* __restrict__ act,
                                             const float* __restrict__ Wp,
                                             const float* __restrict__ bp,
                                             float* __restrict__ rho) {
    __shared__ __align__(16) float actS[4][32];
    __shared__ __align__(16) float Ablk[32 * 68];  // A blocks, [g][r*8+c]
    __shared__ __align__(16) float Esm[32 * 72];   // exp blocks, [g][r*8+c]
    const int tid = threadIdx.x;
    const int bt0 = blockIdx.x * 4;

    for (int i = tid; i < 128; i += 256)
        actS[i >> 5][i & 31] = act[(size_t)bt0 * 32 + i];
    __syncthreads();

    // after_phi = act @ Wp + bp, 2 consecutive j per thread (f32x2 lanes)
    {
        const int j0 = tid * 2;
        unsigned long long wv[32];
#pragma unroll
        for (int a = 0; a < 32; a++)
            wv[a] = *(const unsigned long long*)&Wp[a * 512 + j0];
        const unsigned long long bb2 = *(const unsigned long long*)&bp[j0];
        const int k = j0 >> 6, rowj = (j0 >> 3) & 7, colj = j0 & 7;
#pragma unroll
        for (int lbt = 0; lbt < 4; lbt++) {
            unsigned long long s2 = bb2;
#pragma unroll
            for (int a = 0; a < 32; a++) {
                float av = actS[lbt][a];
                s2 = fma2_(pk2(av, av), wv[a], s2);
            }
            float v0, v1;
            upk2(s2, v0, v1);
            // blocks.transpose(0,2,1): A[colj][rowj] = after_phi[j]
            Ablk[(lbt * 8 + k) * 68 + colj * 8 + rowj] = v0;
            Ablk[(lbt * 8 + k) * 68 + (colj + 1) * 8 + rowj] = v1;
        }
    }
    __syncthreads();

    // expm: group g (8 lanes), lane lc owns column lc. exp(A) = (expT10(A/4))^4
    const int g = tid >> 3, lc = tid & 7;
    unsigned long long A2[8][4];
#pragma unroll
    for (int p = 0; p < 4; p++) {
        float4 a0 = *(const float4*)&Ablk[g * 68 + (2 * p) * 8];
        float4 a1 = *(const float4*)&Ablk[g * 68 + (2 * p) * 8 + 4];
        float4 b0 = *(const float4*)&Ablk[g * 68 + (2 * p + 1) * 8];
        float4 b1 = *(const float4*)&Ablk[g * 68 + (2 * p + 1) * 8 + 4];
        A2[0][p] = pk2(a0.x * 0.25f, b0.x * 0.25f);
        A2[1][p] = pk2(a0.y * 0.25f, b0.y * 0.25f);
        A2[2][p] = pk2(a0.z * 0.25f, b0.z * 0.25f);
        A2[3][p] = pk2(a0.w * 0.25f, b0.w * 0.25f);
        A2[4][p] = pk2(a1.x * 0.25f, b1.x * 0.25f);
        A2[5][p] = pk2(a1.y * 0.25f, b1.y * 0.25f);
        A2[6][p] = pk2(a1.z * 0.25f, b1.z * 0.25f);
        A2[7][p] = pk2(a1.w * 0.25f, b1.w * 0.25f);
    }
    unsigned long long idv[4];
#pragma unroll
    for (int p = 0; p < 4; p++)
        idv[p] = pk2(lc == 2 * p ? 1.0f : 0.0f, lc == 2 * p + 1 ? 1.0f : 0.0f);
    unsigned long long Rc2[4];
#pragma unroll
    for (int p = 0; p < 4; p++) {
        float a0 = Ablk[g * 68 + (2 * p) * 8 + lc] * 0.025f;
        float a1 = Ablk[g * 68 + (2 * p + 1) * 8 + lc] * 0.025f;
        Rc2[p] = pk2(a0 + (lc == 2 * p ? 1.0f : 0.0f),
                     a1 + (lc == 2 * p + 1 ? 1.0f : 0.0f));
    }
#pragma unroll
    for (int m = 9; m >= 1; m--) {   // R <- I + (As*R)/m
        unsigned long long t2[4] = {0, 0, 0, 0};
#pragma unroll
        for (int q = 0; q < 4; q++) {
            float s0, s1;
            upk2(Rc2[q], s0, s1);
            unsigned long long u0 = pk2(s0, s0), u1 = pk2(s1, s1);
#pragma unroll
            for (int p = 0; p < 4; p++) t2[p] = fma2_(A2[2 * q][p], u0, t2[p]);
#pragma unroll
            for (int p = 0; p < 4; p++) t2[p] = fma2_(A2[2 * q + 1][p], u1, t2[p]);
        }
        const float inv = 1.0f / (float)m;
        const unsigned long long inv2 = pk2(inv, inv);
#pragma unroll
        for (int p = 0; p < 4; p++) Rc2[p] = fma2_(t2[p], inv2, idv[p]);
    }
#pragma unroll
    for (int sq = 0; sq < 2; sq++) {   // R <- R*R  (undo the /4 scaling)
        unsigned long long t2[4] = {0, 0, 0, 0};
#pragma unroll
        for (int q = 0; q < 4; q++) {
            float s0, s1;
            upk2(Rc2[q], s0, s1);
            unsigned long long u0 = pk2(s0, s0), u1 = pk2(s1, s1);
#pragma unroll
            for (int p = 0; p < 4; p++) {
                unsigned long long cj = __shfl_sync(0xffffffffu, Rc2[p], 2 * q, 8);
                t2[p] = fma2_(cj, u0, t2[p]);
            }
#pragma unroll
            for (int p = 0; p < 4; p++) {
                unsigned long long cj = __shfl_sync(0xffffffffu, Rc2[p], 2 * q + 1, 8);
                t2[p] = fma2_(cj, u1, t2[p]);
            }
        }
#pragma unroll
        for (int p = 0; p < 4; p++) Rc2[p] = t2[p];
    }
#pragma unroll
    for (int p = 0; p < 4; p++) {
        float e0, e1;
        upk2(Rc2[p], e0, e1);
        Esm[g * 72 + (2 * p) * 8 + lc] = e0;
        Esm[g * 72 + (2 * p + 1) * 8 + lc] = e1;
    }
    __syncthreads();

    // compact column-major copy for recurrence
#pragma unroll
    for (int i = tid; i < 2048; i += 256) {
        int lbt = i >> 9, q = i & 511;
        int k = q >> 6, cq = (q >> 3) & 7, rq = q & 7;
        g_expT[(size_t)(bt0 + lbt) * 512 + q] = Esm[(lbt * 8 + k) * 72 + rq * 8 + cq];
    }
    // rho: fully coalesced streaming float4 (zeros + diagonal blocks)
#pragma unroll
    for (int i = tid; i < 4096; i += 256) {
        int lbt = i >> 10, rem = i & 1023, row = rem >> 4, q = rem & 15;
        int k = row >> 3;
        float4 v = make_float4(0.f, 0.f, 0.f, 0.f);
        if ((q >> 1) == k)
            v = *(const float4*)&Esm[(lbt * 8 + k) * 72 + (row & 7) * 8 + (q & 1) * 4];
        __stcs((float4*)rho + ((size_t)(bt0 + lbt) * 64 + row) * 16 + q, v);
    }
}

// ---------------- recurrence -----------------------------------------------
static __device__ __forceinline__ float stepf(float h, float4 e0, float4 e1) {
    float s0 = __shfl_sync(0xffffffffu, h, 0, 8) * e0.x;
    float s1 = __shfl_sync(0xffffffffu, h, 1, 8) * e0.y;
    s0 = fmaf(__shfl_sync(0xffffffffu, h, 2, 8), e0.z, s0);
    s1 = fmaf(__shfl_sync(0xffffffffu, h, 3, 8), e0.w, s1);
    s0 = fmaf(__shfl_sync(0xffffffffu, h, 4, 8), e1.x, s0);
    s1 = fmaf(__shfl_sync(0xffffffffu, h, 5, 8), e1.y, s1);
    s0 = fmaf(__shfl_sync(0xffffffffu, h, 6, 8), e1.z, s0);
    s1 = fmaf(__shfl_sync(0xffffffffu, h, 7, 8), e1.w, s1);
    return s0 + s1;
}

__global__ void __launch_bounds__(32) k_rec(const float* __restrict__ latent,
                                            float* __restrict__ pred) {
    const int lane = threadIdx.x;
    const int chain = blockIdx.x * 4 + (lane >> 3);  // 0..511
    const int b = chain >> 3, k = chain & 7, cc = lane & 7;
    const size_t pbase = (size_t)b * 256 * 64 + k * 8 + cc;
    float h = latent[pbase];
    pred[pbase] = h;
    const float4* base = (const float4*)g_expT + (size_t)b * 255 * 128 + k * 16 + cc * 2;

    float4 cur[16], nxt[16];
#pragma unroll
    for (int s = 0; s < 8; s++) {
        cur[2 * s] = base[(size_t)s * 128];
        cur[2 * s + 1] = base[(size_t)s * 128 + 1];
    }
    int t = 0;
    for (int gg = 1; gg < 32; gg++) {
#pragma unroll
        for (int s = 0; s < 8; s++) {
            int tt = gg * 8 + s;
            if (tt > 254) tt = 254;
            nxt[2 * s] = base[(size_t)tt * 128];
            nxt[2 * s + 1] = base[(size_t)tt * 128 + 1];
        }
#pragma unroll
        for (int s = 0; s < 8; s++) {
            h = stepf(h, cur[2 * s], cur[2 * s + 1]);
            pred[pbase + (size_t)(t + s + 1) * 64] = h;
        }
        t += 8;
#pragma unroll
        for (int i = 0; i < 16; i++) cur[i] = nxt[i];
    }
#pragma unroll
    for (int s = 0; s < 7; s++) {
        h = stepf(h, cur[2 * s], cur[2 * s + 1]);
        pred[pbase + (size_t)(249 + s) * 64] = h;
    }
}

// ---------------- decoder: pred_obs = pred_lat(16384x64) @ Wd(64x512) + bd --
__global__ void __launch_bounds__(128) k_dec(const float* __restrict__ lat,
                                             const float* __restrict__ Wd,
                                             const float* __restrict__ bd,
                                             float* __restrict__ out) {
    __shared__ __align__(16) float latS[64 * 68];
    __shared__ __align__(16) float Wsm[32 * 128];
    const int tid = threadIdx.x;
    const int tx = tid & 7, ty = tid >> 3;
    const int row0 = blockIdx.x * 64;
    const int col0 = blockIdx.y * 128;
    const int cb = col0 + tx * 16;

#pragma unroll
    for (int n = 0; n < 8; n++) {
        int i = tid + n * 128;
        int rr = i >> 4, c4 = (i & 15) * 4;
        *(float4*)&latS[rr * 68 + c4] =
            *(const float4*)&lat[(size_t)(row0 + rr) * 64 + c4];
    }
    unsigned long long acc[4][8];
    {
#pragma unroll
        for (int q = 0; q < 8; q++) {
            unsigned long long bv = pk2(bd[cb + 2 * q], bd[cb + 2 * q + 1]);
#pragma unroll
            for (int r = 0; r < 4; r++) acc[r][q] = bv;
        }
    }
    for (int chunk = 0; chunk < 2; chunk++) {
        __syncthreads();
#pragma unroll
        for (int n = 0; n < 8; n++) {
            int i = tid + n * 128;
            int rk = i >> 5, c4 = (i & 31) * 4;
            int q = (c4 >> 2) & 3, txc = c4 >> 4;
            *(float4*)&Wsm[rk * 128 + (q * 8 + txc) * 4] =
                *(const float4*)&Wd[(size_t)(chunk * 32 + rk) * 512 + col0 + c4];
        }
        __syncthreads();
#pragma unroll
        for (int k4 = 0; k4 < 8; k4++) {
            float4 o4[4];
#pragma unroll
            for (int r = 0; r < 4; r++)
                o4[r] = *(const float4*)&latS[(ty + r * 16) * 68 + chunk * 32 + k4 * 4];
#pragma unroll
            for (int kk = 0; kk < 4; kk++) {
                int k = k4 * 4 + kk;
                ulonglong2 w0 = *(const ulonglong2*)&Wsm[k * 128 + tx * 4];
                ulonglong2 w1 = *(const ulonglong2*)&Wsm[k * 128 + (8 + tx) * 4];
                ulonglong2 w2 = *(const ulonglong2*)&Wsm[k * 128 + (16 + tx) * 4];
                ulonglong2 w3 = *(const ulonglong2*)&Wsm[k * 128 + (24 + tx) * 4];
#pragma unroll
                for (int r = 0; r < 4; r++) {
                    float o = (kk == 0) ? o4[r].x : (kk == 1) ? o4[r].y
                              : (kk == 2) ? o4[r].z : o4[r].w;
                    unsigned long long o2 = pk2(o, o);
                    acc[r][0] = fma2_(o2, w0.x, acc[r][0]);
                    acc[r][1] = fma2_(o2, w0.y, acc[r][1]);
                    acc[r][2] = fma2_(o2, w1.x, acc[r][2]);
                    acc[r][3] = fma2_(o2, w1.y, acc[r][3]);
                    acc[r][4] = fma2_(o2, w2.x, acc[r][4]);
                    acc[r][5] = fma2_(o2, w2.y, acc[r][5]);
                    acc[r][6] = fma2_(o2, w3.x, acc[r][6]);
                    acc[r][7] = fma2_(o2, w3.y, acc[r][7]);
                }
            }
        }
    }
#pragma unroll
    for (int r = 0; r < 4; r++) {
        float* dst = &out[(size_t)(row0 + ty + r * 16) * 512 + cb];
#pragma unroll
        for (int q = 0; q < 4; q++) {
            float v0, v1, v2, v3;
            upk2(acc[r][2 * q], v0, v1);
            upk2(acc[r][2 * q + 1], v2, v3);
            __stcs((float4*)(dst + q * 4), make_float4(v0, v1, v2, v3));
        }
    }
}

extern "C" void kernel_launch(void* const* d_in, const int* in_sizes, int n_in,
                              void* d_out, int out_size) {
    const float* obs = (const float*)d_in[0];
    const float* act = (const float*)d_in[1];
    const float* We  = (const float*)d_in[2];
    const float* be  = (const float*)d_in[3];
    const float* Wd  = (const float*)d_in[4];
    const float* bd  = (const float*)d_in[5];
    const float* Wp  = (const float*)d_in[6];
    const float* bp  = (const float*)d_in[7];
    float* out = (float*)d_out;

    float* latent   = out;                 // [64,256,64]
    float* rho      = out + 1048576;       // [64,255,64,64]
    float* pred_lat = out + 67895296;      // [64,256,64]
    float* pred_obs = out + 68943872;      // [64,256,512]

    k_enc<<<256, 128>>>(obs, We, be, latent);
    k_phi<<<4080, 256>>>(act, Wp, bp, rho);
    k_rec<<<128, 32>>>(latent, pred_lat);
    k_dec<<<dim3(256, 4), 128>>>(pred_lat, Wd, bd, pred_obs);
}

// round 9
// speedup vs baseline: 2.0047x; 1.0350x over previous
#include <cuda_runtime.h>

#define NBT 16320  // 64 * 255

// compact exp blocks: g_expT[bt*512 + k*64 + c*8 + r] = E_k[r][c], bt = b*255+t
__device__ float g_expT[NBT * 512];

static __device__ __forceinline__ unsigned long long pk2(float lo, float hi) {
    unsigned long long r;
    asm("mov.b64 %0, {%1,%2};" : "=l"(r) : "f"(lo), "f"(hi));
    return r;
}
static __device__ __forceinline__ void upk2(unsigned long long v, float& lo, float& hi) {
    asm("mov.b64 {%0,%1}, %2;" : "=f"(lo), "=f"(hi) : "l"(v));
}
static __device__ __forceinline__ unsigned long long fma2_(unsigned long long a,
                                                           unsigned long long b,
                                                           unsigned long long c) {
    unsigned long long d;
    asm("fma.rn.f32x2 %0, %1, %2, %3;" : "=l"(d) : "l"(a), "l"(b), "l"(c));
    return d;
}

// ---------------- encoder: latent = obs(16384x512) @ We(512x64) + be -------
// 64x64 tile, 128 thr, thread = 8 rows x 4 cols. Register double-buffered K
// chunks of 64. W in natural layout: cols tx*4 contiguous -> conflict-free.
__global__ void __launch_bounds__(128) k_enc(const float* __restrict__ obs,
                                             const float* __restrict__ We,
                                             const float* __restrict__ be,
                                             float* __restrict__ latent) {
    __shared__ __align__(16) float obsS[64 * 68];
    __shared__ __align__(16) float Wsm[64 * 64];
    const int tid = threadIdx.x;
    const int tx = tid & 15, ty = tid >> 4;   // tx: col group (4 cols), ty: 0..7
    const int row0 = blockIdx.x * 64;
    const int cb = tx * 4;

    unsigned long long acc[8][2];
    {
        unsigned long long b0 = pk2(be[cb + 0], be[cb + 1]);
        unsigned long long b1 = pk2(be[cb + 2], be[cb + 3]);
#pragma unroll
        for (int r = 0; r < 8; r++) { acc[r][0] = b0; acc[r][1] = b1; }
    }

    float4 rA[8], rW[8];
#pragma unroll
    for (int n = 0; n < 8; n++) {
        int i = tid + n * 128;
        int rr = i >> 4, c4 = (i & 15) * 4;
        rA[n] = *(const float4*)&obs[(size_t)(row0 + rr) * 512 + c4];
        rW[n] = *(const float4*)&We[(size_t)rr * 64 + c4];
    }
    for (int kc = 0; kc < 8; kc++) {
#pragma unroll
        for (int n = 0; n < 8; n++) {
            int i = tid + n * 128;
            int rr = i >> 4, c4 = (i & 15) * 4;
            *(float4*)&obsS[rr * 68 + c4] = rA[n];
            *(float4*)&Wsm[rr * 64 + c4] = rW[n];
        }
        __syncthreads();
        if (kc < 7) {
#pragma unroll
            for (int n = 0; n < 8; n++) {
                int i = tid + n * 128;
                int rr = i >> 4, c4 = (i & 15) * 4;
                rA[n] = *(const float4*)&obs[(size_t)(row0 + rr) * 512 + (kc + 1) * 64 + c4];
                rW[n] = *(const float4*)&We[(size_t)((kc + 1) * 64 + rr) * 64 + c4];
            }
        }
#pragma unroll
        for (int k4 = 0; k4 < 16; k4++) {
            float4 o4[8];
#pragma unroll
            for (int r = 0; r < 8; r++)
                o4[r] = *(const float4*)&obsS[(ty + r * 8) * 68 + k4 * 4];
#pragma unroll
            for (int kk = 0; kk < 4; kk++) {
                int k = k4 * 4 + kk;
                ulonglong2 w = *(const ulonglong2*)&Wsm[k * 64 + tx * 4];
#pragma unroll
                for (int r = 0; r < 8; r++) {
                    float o = (kk == 0) ? o4[r].x : (kk == 1) ? o4[r].y
                              : (kk == 2) ? o4[r].z : o4[r].w;
                    unsigned long long o2 = pk2(o, o);
                    acc[r][0] = fma2_(o2, w.x, acc[r][0]);
                    acc[r][1] = fma2_(o2, w.y, acc[r][1]);
                }
            }
        }
        __syncthreads();
    }
#pragma unroll
    for (int r = 0; r < 8; r++) {
        float v0, v1, v2, v3;
        upk2(acc[r][0], v0, v1); upk2(acc[r][1], v2, v3);
        *(float4*)&latent[(size_t)(row0 + ty + r * 8) * 64 + cb] =
            make_float4(v0, v1, v2, v3);
    }
}

// ---------------- phi GEMM + expm + rho ------------------------------------
__global__ void __launch_bounds__(256) k_phi(const float* __restrict__ act,
                                             const float* __restrict__ Wp,
                                             const float* __restrict__ bp,
                                             float* __restrict__ rho) {
    __shared__ __align__(16) float actS[4][32];
    __shared__ __align__(16) float Ablk[32 * 68];  // A blocks, [g][r*8+c]
    __shared__ __align__(16) float Esm[32 * 72];   // exp blocks, [g][r*8+c]
    const int tid = threadIdx.x;
    const int bt0 = blockIdx.x * 4;

    for (int i = tid; i < 128; i += 256)
        actS[i >> 5][i & 31] = act[(size_t)bt0 * 32 + i];
    __syncthreads();

    // after_phi = act @ Wp + bp, 2 consecutive j per thread (f32x2 lanes)
    {
        const int j0 = tid * 2;
        unsigned long long wv[32];
#pragma unroll
        for (int a = 0; a < 32; a++)
            wv[a] = *(const unsigned long long*)&Wp[a * 512 + j0];
        const unsigned long long bb2 = *(const unsigned long long*)&bp[j0];
        const int k = j0 >> 6, rowj = (j0 >> 3) & 7, colj = j0 & 7;
#pragma unroll
        for (int lbt = 0; lbt < 4; lbt++) {
            unsigned long long s2 = bb2;
#pragma unroll
            for (int a = 0; a < 32; a++) {
                float av = actS[lbt][a];
                s2 = fma2_(pk2(av, av), wv[a], s2);
            }
            float v0, v1;
            upk2(s2, v0, v1);
            // blocks.transpose(0,2,1): A[colj][rowj] = after_phi[j]
            Ablk[(lbt * 8 + k) * 68 + colj * 8 + rowj] = v0;
            Ablk[(lbt * 8 + k) * 68 + (colj + 1) * 8 + rowj] = v1;
        }
    }
    __syncthreads();

    // expm: group g (8 lanes), lane lc owns column lc. exp(A) = (expT10(A/4))^4
    const int g = tid >> 3, lc = tid & 7;
    unsigned long long A2[8][4];
#pragma unroll
    for (int p = 0; p < 4; p++) {
        float4 a0 = *(const float4*)&Ablk[g * 68 + (2 * p) * 8];
        float4 a1 = *(const float4*)&Ablk[g * 68 + (2 * p) * 8 + 4];
        float4 b0 = *(const float4*)&Ablk[g * 68 + (2 * p + 1) * 8];
        float4 b1 = *(const float4*)&Ablk[g * 68 + (2 * p + 1) * 8 + 4];
        A2[0][p] = pk2(a0.x * 0.25f, b0.x * 0.25f);
        A2[1][p] = pk2(a0.y * 0.25f, b0.y * 0.25f);
        A2[2][p] = pk2(a0.z * 0.25f, b0.z * 0.25f);
        A2[3][p] = pk2(a0.w * 0.25f, b0.w * 0.25f);
        A2[4][p] = pk2(a1.x * 0.25f, b1.x * 0.25f);
        A2[5][p] = pk2(a1.y * 0.25f, b1.y * 0.25f);
        A2[6][p] = pk2(a1.z * 0.25f, b1.z * 0.25f);
        A2[7][p] = pk2(a1.w * 0.25f, b1.w * 0.25f);
    }
    unsigned long long idv[4];
#pragma unroll
    for (int p = 0; p < 4; p++)
        idv[p] = pk2(lc == 2 * p ? 1.0f : 0.0f, lc == 2 * p + 1 ? 1.0f : 0.0f);
    unsigned long long Rc2[4];
#pragma unroll
    for (int p = 0; p < 4; p++) {
        float a0 = Ablk[g * 68 + (2 * p) * 8 + lc] * 0.025f;
        float a1 = Ablk[g * 68 + (2 * p + 1) * 8 + lc] * 0.025f;
        Rc2[p] = pk2(a0 + (lc == 2 * p ? 1.0f : 0.0f),
                     a1 + (lc == 2 * p + 1 ? 1.0f : 0.0f));
    }
#pragma unroll
    for (int m = 9; m >= 1; m--) {   // R <- I + (As*R)/m
        unsigned long long t2[4] = {0, 0, 0, 0};
#pragma unroll
        for (int q = 0; q < 4; q++) {
            float s0, s1;
            upk2(Rc2[q], s0, s1);
            unsigned long long u0 = pk2(s0, s0), u1 = pk2(s1, s1);
#pragma unroll
            for (int p = 0; p < 4; p++) t2[p] = fma2_(A2[2 * q][p], u0, t2[p]);
#pragma unroll
            for (int p = 0; p < 4; p++) t2[p] = fma2_(A2[2 * q + 1][p], u1, t2[p]);
        }
        const float inv = 1.0f / (float)m;
        const unsigned long long inv2 = pk2(inv, inv);
#pragma unroll
        for (int p = 0; p < 4; p++) Rc2[p] = fma2_(t2[p], inv2, idv[p]);
    }
#pragma unroll
    for (int sq = 0; sq < 2; sq++) {   // R <- R*R  (undo the /4 scaling)
        unsigned long long t2[4] = {0, 0, 0, 0};
#pragma unroll
        for (int q = 0; q < 4; q++) {
            float s0, s1;
            upk2(Rc2[q], s0, s1);
            unsigned long long u0 = pk2(s0, s0), u1 = pk2(s1, s1);
#pragma unroll
            for (int p = 0; p < 4; p++) {
                unsigned long long cj = __shfl_sync(0xffffffffu, Rc2[p], 2 * q, 8);
                t2[p] = fma2_(cj, u0, t2[p]);
            }
#pragma unroll
            for (int p = 0; p < 4; p++) {
                unsigned long long cj = __shfl_sync(0xffffffffu, Rc2[p], 2 * q + 1, 8);
                t2[p] = fma2_(cj, u1, t2[p]);
            }
        }
#pragma unroll
        for (int p = 0; p < 4; p++) Rc2[p] = t2[p];
    }
#pragma unroll
    for (int p = 0; p < 4; p++) {
        float e0, e1;
        upk2(Rc2[p], e0, e1);
        Esm[g * 72 + (2 * p) * 8 + lc] = e0;
        Esm[g * 72 + (2 * p + 1) * 8 + lc] = e1;
    }
    __syncthreads();

    // compact column-major copy for recurrence
#pragma unroll
    for (int i = tid; i < 2048; i += 256) {
        int lbt = i >> 9, q = i & 511;
        int k = q >> 6, cq = (q >> 3) & 7, rq = q & 7;
        g_expT[(size_t)(bt0 + lbt) * 512 + q] = Esm[(lbt * 8 + k) * 72 + rq * 8 + cq];
    }
    // rho: fully coalesced streaming float4 (zeros + diagonal blocks)
#pragma unroll
    for (int i = tid; i < 4096; i += 256) {
        int lbt = i >> 10, rem = i & 1023, row = rem >> 4, q = rem & 15;
        int k = row >> 3;
        float4 v = make_float4(0.f, 0.f, 0.f, 0.f);
        if ((q >> 1) == k)
            v = *(const float4*)&Esm[(lbt * 8 + k) * 72 + (row & 7) * 8 + (q & 1) * 4];
        __stcs((float4*)rho + ((size_t)(bt0 + lbt) * 64 + row) * 16 + q, v);
    }
}

// ---------------- recurrence -----------------------------------------------
static __device__ __forceinline__ float stepf(float h, float4 e0, float4 e1) {
    float s0 = __shfl_sync(0xffffffffu, h, 0, 8) * e0.x;
    float s1 = __shfl_sync(0xffffffffu, h, 1, 8) * e0.y;
    s0 = fmaf(__shfl_sync(0xffffffffu, h, 2, 8), e0.z, s0);
    s1 = fmaf(__shfl_sync(0xffffffffu, h, 3, 8), e0.w, s1);
    s0 = fmaf(__shfl_sync(0xffffffffu, h, 4, 8), e1.x, s0);
    s1 = fmaf(__shfl_sync(0xffffffffu, h, 5, 8), e1.y, s1);
    s0 = fmaf(__shfl_sync(0xffffffffu, h, 6, 8), e1.z, s0);
    s1 = fmaf(__shfl_sync(0xffffffffu, h, 7, 8), e1.w, s1);
    return s0 + s1;
}

__global__ void __launch_bounds__(32) k_rec(const float* __restrict__ latent,
                                            float* __restrict__ pred) {
    const int lane = threadIdx.x;
    const int chain = blockIdx.x * 4 + (lane >> 3);  // 0..511
    const int b = chain >> 3, k = chain & 7, cc = lane & 7;
    const size_t pbase = (size_t)b * 256 * 64 + k * 8 + cc;
    float h = latent[pbase];
    pred[pbase] = h;
    const float4* base = (const float4*)g_expT + (size_t)b * 255 * 128 + k * 16 + cc * 2;

    float4 cur[16], nxt[16];
#pragma unroll
    for (int s = 0; s < 8; s++) {
        cur[2 * s] = base[(size_t)s * 128];
        cur[2 * s + 1] = base[(size_t)s * 128 + 1];
    }
    int t = 0;
    for (int gg = 1; gg < 32; gg++) {
#pragma unroll
        for (int s = 0; s < 8; s++) {
            int tt = gg * 8 + s;
            if (tt > 254) tt = 254;
            nxt[2 * s] = base[(size_t)tt * 128];
            nxt[2 * s + 1] = base[(size_t)tt * 128 + 1];
        }
#pragma unroll
        for (int s = 0; s < 8; s++) {
            h = stepf(h, cur[2 * s], cur[2 * s + 1]);
            pred[pbase + (size_t)(t + s + 1) * 64] = h;
        }
        t += 8;
#pragma unroll
        for (int i = 0; i < 16; i++) cur[i] = nxt[i];
    }
#pragma unroll
    for (int s = 0; s < 7; s++) {
        h = stepf(h, cur[2 * s], cur[2 * s + 1]);
        pred[pbase + (size_t)(249 + s) * 64] = h;
    }
}

// ---------------- decoder: pred_obs = pred_lat(16384x64) @ Wd(64x512) + bd --
// 128x128 tile, 256 thr, thread = 8 rows x 8 cols, K=64 loaded once.
// W row layout: [f4 group0 of tx0..15][f4 group1 of tx0..15] -> conflict-free.
__global__ void __launch_bounds__(256) k_dec(const float* __restrict__ lat,
                                             const float* __restrict__ Wd,
                                             const float* __restrict__ bd,
                                             float* __restrict__ out) {
    __shared__ __align__(16) float latS[128 * 68];
    __shared__ __align__(16) float Wsm[64 * 128];
    const int tid = threadIdx.x;
    const int tx = tid & 15, ty = tid >> 4;   // tx: col group (8 cols), ty: 0..15
    const int row0 = blockIdx.x * 128;
    const int col0 = blockIdx.y * 128;
    const int cb = col0 + tx * 8;

#pragma unroll
    for (int n = 0; n < 8; n++) {
        int i = tid + n * 256;
        int rr = i >> 4, c4 = (i & 15) * 4;
        *(float4*)&latS[rr * 68 + c4] =
            *(const float4*)&lat[(size_t)(row0 + rr) * 64 + c4];
    }
#pragma unroll
    for (int n = 0; n < 8; n++) {
        int i = tid + n * 256;
        int rk = i >> 5, c4 = (i & 31) * 4;
        int txc = c4 >> 3, q = (c4 >> 2) & 1;
        *(float4*)&Wsm[rk * 128 + q * 64 + txc * 4] =
            *(const float4*)&Wd[(size_t)rk * 512 + col0 + c4];
    }
    unsigned long long acc[8][4];
#pragma unroll
    for (int j = 0; j < 4; j++) {
        unsigned long long bv = pk2(bd[cb + 2 * j], bd[cb + 2 * j + 1]);
#pragma unroll
        for (int r = 0; r < 8; r++) acc[r][j] = bv;
    }
    __syncthreads();
#pragma unroll
    for (int k4 = 0; k4 < 16; k4++) {
        float4 o4[8];
#pragma unroll
        for (int r = 0; r < 8; r++)
            o4[r] = *(const float4*)&latS[(ty + r * 16) * 68 + k4 * 4];
#pragma unroll
        for (int kk = 0; kk < 4; kk++) {
            int k = k4 * 4 + kk;
            ulonglong2 w0 = *(const ulonglong2*)&Wsm[k * 128 + tx * 4];
            ulonglong2 w1 = *(const ulonglong2*)&Wsm[k * 128 + 64 + tx * 4];
#pragma unroll
            for (int r = 0; r < 8; r++) {
                float o = (kk == 0) ? o4[r].x : (kk == 1) ? o4[r].y
                          : (kk == 2) ? o4[r].z : o4[r].w;
                unsigned long long o2 = pk2(o, o);
                acc[r][0] = fma2_(o2, w0.x, acc[r][0]);
                acc[r][1] = fma2_(o2, w0.y, acc[r][1]);
                acc[r][2] = fma2_(o2, w1.x, acc[r][2]);
                acc[r][3] = fma2_(o2, w1.y, acc[r][3]);
            }
        }
    }
#pragma unroll
    for (int r = 0; r < 8; r++) {
        float v0, v1, v2, v3, v4, v5, v6, v7;
        upk2(acc[r][0], v0, v1); upk2(acc[r][1], v2, v3);
        upk2(acc[r][2], v4, v5); upk2(acc[r][3], v6, v7);
        float* dst = &out[(size_t)(row0 + ty + r * 16) * 512 + cb];
        __stcs((float4*)dst, make_float4(v0, v1, v2, v3));
        __stcs((float4*)(dst + 4), make_float4(v4, v5, v6, v7));
    }
}

extern "C" void kernel_launch(void* const* d_in, const int* in_sizes, int n_in,
                              void* d_out, int out_size) {
    const float* obs = (const float*)d_in[0];
    const float* act = (const float*)d_in[1];
    const float* We  = (const float*)d_in[2];
    const float* be  = (const float*)d_in[3];
    const float* Wd  = (const float*)d_in[4];
    const float* bd  = (const float*)d_in[5];
    const float* Wp  = (const float*)d_in[6];
    const float* bp  = (const float*)d_in[7];
    float* out = (float*)d_out;

    float* latent   = out;                 // [64,256,64]
    float* rho      = out + 1048576;       // [64,255,64,64]
    float* pred_lat = out + 67895296;      // [64,256,64]
    float* pred_obs = out + 68943872;      // [64,256,512]

    k_enc<<<256, 128>>>(obs, We, be, latent);
    k_phi<<<4080, 256>>>(act, Wp, bp, rho);
    k_rec<<<128, 32>>>(latent, pred_lat);
    k_dec<<<dim3(128, 4), 256>>>(pred_lat, Wd, bd, pred_obs);
}